// round 5
// baseline (speedup 1.0000x reference)
#include <cuda_runtime.h>

typedef unsigned long long u64;

#define NMAX_NODES 100000

#define SH_C0 0.28209479177387814f
#define SH_C1 0.48860251190291992f
#define SH_C2 1.09254843059207907f
#define SH_C3 0.31539156525252005f
#define SH_C4 0.54627421529603953f

// scratch: per-node aggregated edge messages (100000 x 64 f32 = 25.6 MB)
__device__ __align__(16) float g_agg[NMAX_NODES * 64];

// ---------------- packed f32x2 helpers (Blackwell FFMA2) ----------------
__device__ __forceinline__ u64 pack2(float lo, float hi) {
    u64 r; asm("mov.b64 %0, {%1, %2};" : "=l"(r) : "f"(lo), "f"(hi)); return r;
}
__device__ __forceinline__ float2 unpack2(u64 v) {
    float2 f; asm("mov.b64 {%0, %1}, %2;" : "=f"(f.x), "=f"(f.y) : "l"(v)); return f;
}
__device__ __forceinline__ u64 fma2(u64 a, u64 b, u64 c) {
    u64 d; asm("fma.rn.f32x2 %0, %1, %2, %3;" : "=l"(d) : "l"(a), "l"(b), "l"(c)); return d;
}
__device__ __forceinline__ void red4(float* p, float a, float b, float c, float d) {
    asm volatile("red.global.add.v4.f32 [%0], {%1, %2, %3, %4};"
                 :: "l"(p), "f"(a), "f"(b), "f"(c), "f"(d) : "memory");
}
__device__ __forceinline__ float siluf(float x) { return x / (1.0f + __expf(-x)); }

// ---------------- kernel 0: zero the aggregation buffer ----------------
__global__ void zero_agg_kernel(int n4) {
    float4 z = make_float4(0.f, 0.f, 0.f, 0.f);
    float4* p = reinterpret_cast<float4*>(g_agg);
    for (int i = blockIdx.x * blockDim.x + threadIdx.x; i < n4; i += gridDim.x * blockDim.x)
        p[i] = z;
}

// ---------------- kernel 1: per-edge MLP + scatter-add -----------------
// shared layout (floats)
#define E_W1  0      // 32*64
#define E_W2  2048   // 64*64
#define E_B1  6144   // 64
#define E_B2  6208   // 64
#define E_CEN 6272   // 16
#define E_WID 6288   // 16
#define E_SHW 6304   // 9*16
#define E_SHB 6448   // 16
#define E_TOT 6464

__global__ __launch_bounds__(128)
void edge_kernel(const float* __restrict__ pos, const int* __restrict__ ei,
                 const float* __restrict__ cen, const float* __restrict__ wid,
                 const float* __restrict__ shw, const float* __restrict__ shb,
                 const float* __restrict__ w1, const float* __restrict__ b1,
                 const float* __restrict__ w2, const float* __restrict__ b2,
                 int E)
{
    __shared__ __align__(16) float S[E_TOT];
    const int t = threadIdx.x;
    for (int i = t; i < 2048; i += 128) S[E_W1 + i] = w1[i];
    for (int i = t; i < 4096; i += 128) S[E_W2 + i] = w2[i];
    if (t < 64) { S[E_B1 + t] = b1[t]; S[E_B2 + t] = b2[t]; }
    if (t < 16) { S[E_CEN + t] = cen[t]; S[E_WID + t] = wid[t]; S[E_SHB + t] = shb[t]; }
    for (int i = t; i < 144; i += 128) S[E_SHW + i] = shw[i];
    __syncthreads();

    for (int e = blockIdx.x * 128 + t; e < E; e += gridDim.x * 128) {
        const int si = ei[e];
        const int di = ei[E + e];

        float rx = pos[3 * di]     - pos[3 * si];
        float ry = pos[3 * di + 1] - pos[3 * si + 1];
        float rz = pos[3 * di + 2] - pos[3 * si + 2];
        float d = sqrtf(rx * rx + ry * ry + rz * rz);
        d = fmaxf(d, 1e-6f);
        float inv = 1.0f / d;
        float ux = rx * inv, uy = ry * inv, uz = rz * inv;

        float feat[32];
#pragma unroll
        for (int k = 0; k < 16; k++) {
            float dd = d - S[E_CEN + k];
            feat[k] = __expf(-fabsf(S[E_WID + k]) * dd * dd);
        }
        float Y[9];
        Y[0] = SH_C0;
        Y[1] = SH_C1 * uy;
        Y[2] = SH_C1 * uz;
        Y[3] = SH_C1 * ux;
        Y[4] = SH_C2 * ux * uy;
        Y[5] = SH_C2 * uy * uz;
        Y[6] = SH_C3 * (2.f * uz * uz - ux * ux - uy * uy);
        Y[7] = SH_C2 * ux * uz;
        Y[8] = SH_C4 * (ux * ux - uy * uy);
#pragma unroll
        for (int k = 0; k < 16; k++) {
            float a = S[E_SHB + k];
#pragma unroll
            for (int i = 0; i < 9; i++) a = fmaf(Y[i], S[E_SHW + i * 16 + k], a);
            feat[16 + k] = a;
        }

        // layer 1: 32 -> 64 (packed f32x2 accumulators)
        u64 h1p[32];
#pragma unroll
        for (int j = 0; j < 32; j++) h1p[j] = *(const u64*)&S[E_B1 + 2 * j];
#pragma unroll
        for (int k = 0; k < 32; k++) {
            u64 fk = pack2(feat[k], feat[k]);
            const longlong2* W = (const longlong2*)&S[E_W1 + k * 64];
#pragma unroll
            for (int j = 0; j < 16; j++) {
                longlong2 wv = W[j];
                h1p[2 * j]     = fma2(fk, (u64)wv.x, h1p[2 * j]);
                h1p[2 * j + 1] = fma2(fk, (u64)wv.y, h1p[2 * j + 1]);
            }
        }
        float a1[64];
#pragma unroll
        for (int j = 0; j < 32; j++) {
            float2 v = unpack2(h1p[j]);
            a1[2 * j]     = siluf(v.x);
            a1[2 * j + 1] = siluf(v.y);
        }

        // layer 2: 64 -> 64, computed in two halves of 32 cols; scatter by SRC
        float* aggp = g_agg + si * 64;
#pragma unroll
        for (int h = 0; h < 2; h++) {
            u64 pfp[16];
#pragma unroll
            for (int j = 0; j < 16; j++) pfp[j] = *(const u64*)&S[E_B2 + h * 32 + 2 * j];
#pragma unroll
            for (int k = 0; k < 64; k++) {
                u64 fk = pack2(a1[k], a1[k]);
                const longlong2* W = (const longlong2*)&S[E_W2 + k * 64 + h * 32];
#pragma unroll
                for (int j = 0; j < 8; j++) {
                    longlong2 wv = W[j];
                    pfp[2 * j]     = fma2(fk, (u64)wv.x, pfp[2 * j]);
                    pfp[2 * j + 1] = fma2(fk, (u64)wv.y, pfp[2 * j + 1]);
                }
            }
#pragma unroll
            for (int m = 0; m < 8; m++) {
                float2 a = unpack2(pfp[2 * m]);
                float2 b = unpack2(pfp[2 * m + 1]);
                red4(aggp + h * 32 + 4 * m, a.x, a.y, b.x, b.y);
            }
        }
    }
}

// ---------------- kernel 2: per-node branch + concat GEMM + LN + silu ----
// dynamic shared layout (floats)
#define N_NPW 0        // 128*128
#define N_ZNW 16384    // 32*64
#define N_ZNB 18432    // 64
#define N_NPB 18496    // 128
#define N_LNG 18624    // 128
#define N_LNB 18752    // 128
#define N_CEN 18880    // 16
#define N_WID 18896    // 16
#define N_SHW 18912    // 144
#define N_SHB 19056    // 16
#define N_XO  19072    // 8 warps * 4 nodes * 128
#define N_FO  23168    // 8 warps * 32
#define N_TOT 23424
#define N_SMEM_BYTES (N_TOT * 4)

__global__ __launch_bounds__(256)
void node_kernel(const float* __restrict__ pos, const float* __restrict__ zinc,
                 const float* __restrict__ cen, const float* __restrict__ wid,
                 const float* __restrict__ shw, const float* __restrict__ shb,
                 const float* __restrict__ znw, const float* __restrict__ znb,
                 const float* __restrict__ npw, const float* __restrict__ npb,
                 const float* __restrict__ lng, const float* __restrict__ lnb,
                 float* __restrict__ out, int N)
{
    extern __shared__ __align__(16) float SD[];
    const int t = threadIdx.x;
    const int w = t >> 5;
    const int lane = t & 31;

    for (int i = t; i < 16384; i += 256) SD[N_NPW + i] = npw[i];
    for (int i = t; i < 2048; i += 256) SD[N_ZNW + i] = znw[i];
    if (t < 64) SD[N_ZNB + t] = znb[t];
    if (t < 128) { SD[N_NPB + t] = npb[t]; SD[N_LNG + t] = lng[t]; SD[N_LNB + t] = lnb[t]; }
    if (t < 16) { SD[N_CEN + t] = cen[t]; SD[N_WID + t] = wid[t]; SD[N_SHB + t] = shb[t]; }
    for (int i = t; i < 144; i += 256) SD[N_SHW + i] = shw[i];
    __syncthreads();

    const float zx = zinc[0], zy = zinc[1], zz = zinc[2];
    float* X = SD + N_XO + w * 512;   // 4 nodes x 128
    float* F = SD + N_FO + w * 32;

    const int wg = blockIdx.x * 8 + w;
    const int nW = gridDim.x * 8;

    for (int base = wg * 4; base < N; base += nW * 4) {
        __syncwarp();
#pragma unroll
        for (int n = 0; n < 4; n++) {
            int node = base + n;
            if (node < N) {
                float rx = pos[3 * node]     - zx;
                float ry = pos[3 * node + 1] - zy;
                float rz = pos[3 * node + 2] - zz;
                float d = sqrtf(rx * rx + ry * ry + rz * rz);
                d = fmaxf(d, 1e-6f);
                float inv = 1.0f / d;
                float ux = rx * inv, uy = ry * inv, uz = rz * inv;

                float f;
                if (lane < 16) {
                    float dd = d - SD[N_CEN + lane];
                    f = __expf(-fabsf(SD[N_WID + lane]) * dd * dd);
                } else {
                    int c = lane - 16;
                    float Y[9];
                    Y[0] = SH_C0;
                    Y[1] = SH_C1 * uy;
                    Y[2] = SH_C1 * uz;
                    Y[3] = SH_C1 * ux;
                    Y[4] = SH_C2 * ux * uy;
                    Y[5] = SH_C2 * uy * uz;
                    Y[6] = SH_C3 * (2.f * uz * uz - ux * ux - uy * uy);
                    Y[7] = SH_C2 * ux * uz;
                    Y[8] = SH_C4 * (ux * ux - uy * uy);
                    f = SD[N_SHB + c];
#pragma unroll
                    for (int i = 0; i < 9; i++) f = fmaf(Y[i], SD[N_SHW + i * 16 + c], f);
                }
                __syncwarp();
                F[lane] = f;
                __syncwarp();

                float z0 = SD[N_ZNB + lane];
                float z1 = SD[N_ZNB + 32 + lane];
#pragma unroll
                for (int k = 0; k < 32; k++) {
                    float fk = F[k];
                    z0 = fmaf(fk, SD[N_ZNW + k * 64 + lane], z0);
                    z1 = fmaf(fk, SD[N_ZNW + k * 64 + 32 + lane], z1);
                }
                X[n * 128 + 64 + lane] = siluf(z0);
                X[n * 128 + 96 + lane] = siluf(z1);
                const float* ag = g_agg + node * 64;
                X[n * 128 + lane]      = ag[lane];
                X[n * 128 + 32 + lane] = ag[32 + lane];
            }
        }
        __syncwarp();

        // concat GEMM: 4 nodes, each lane owns output cols 4*lane..4*lane+3
        u64 acc[4][2];
#pragma unroll
        for (int n = 0; n < 4; n++) {
            acc[n][0] = *(const u64*)&SD[N_NPB + 4 * lane];
            acc[n][1] = *(const u64*)&SD[N_NPB + 4 * lane + 2];
        }
#pragma unroll 8
        for (int k = 0; k < 128; k++) {
            longlong2 wv = ((const longlong2*)&SD[N_NPW + k * 128])[lane];
#pragma unroll
            for (int n = 0; n < 4; n++) {
                u64 fk = pack2(X[n * 128 + k], X[n * 128 + k]);
                acc[n][0] = fma2(fk, (u64)wv.x, acc[n][0]);
                acc[n][1] = fma2(fk, (u64)wv.y, acc[n][1]);
            }
        }

        // layernorm + silu + store
#pragma unroll
        for (int n = 0; n < 4; n++) {
            int node = base + n;
            if (node < N) {
                float2 a = unpack2(acc[n][0]);
                float2 b = unpack2(acc[n][1]);
                float s1 = a.x + a.y + b.x + b.y;
                float s2 = a.x * a.x + a.y * a.y + b.x * b.x + b.y * b.y;
#pragma unroll
                for (int off = 16; off > 0; off >>= 1) {
                    s1 += __shfl_xor_sync(0xffffffffu, s1, off);
                    s2 += __shfl_xor_sync(0xffffffffu, s2, off);
                }
                float mu = s1 * (1.0f / 128.0f);
                float var = s2 * (1.0f / 128.0f) - mu * mu;
                float rstd = rsqrtf(var + 1e-5f);
                float4 o;
                o.x = siluf((a.x - mu) * rstd * SD[N_LNG + 4 * lane]     + SD[N_LNB + 4 * lane]);
                o.y = siluf((a.y - mu) * rstd * SD[N_LNG + 4 * lane + 1] + SD[N_LNB + 4 * lane + 1]);
                o.z = siluf((b.x - mu) * rstd * SD[N_LNG + 4 * lane + 2] + SD[N_LNB + 4 * lane + 2]);
                o.w = siluf((b.y - mu) * rstd * SD[N_LNG + 4 * lane + 3] + SD[N_LNB + 4 * lane + 3]);
                *(float4*)&out[(size_t)node * 128 + 4 * lane] = o;
            }
        }
    }
}

// ---------------- launch ----------------
extern "C" void kernel_launch(void* const* d_in, const int* in_sizes, int n_in,
                              void* d_out, int out_size)
{
    const float* pos  = (const float*)d_in[0];
    const float* zinc = (const float*)d_in[1];
    const int*   ei   = (const int*)  d_in[2];
    const float* cen  = (const float*)d_in[3];
    const float* wid  = (const float*)d_in[4];
    const float* shw  = (const float*)d_in[5];
    const float* shb  = (const float*)d_in[6];
    const float* w1   = (const float*)d_in[7];
    const float* b1   = (const float*)d_in[8];
    const float* w2   = (const float*)d_in[9];
    const float* b2   = (const float*)d_in[10];
    const float* znw  = (const float*)d_in[11];
    const float* znb  = (const float*)d_in[12];
    const float* npw  = (const float*)d_in[13];
    const float* npb  = (const float*)d_in[14];
    const float* lng  = (const float*)d_in[15];
    const float* lnb  = (const float*)d_in[16];

    const int N = in_sizes[0] / 3;
    const int E = in_sizes[2] / 2;

    cudaFuncSetAttribute(node_kernel, cudaFuncAttributeMaxDynamicSharedMemorySize,
                         N_SMEM_BYTES);

    zero_agg_kernel<<<2048, 256>>>(N * 16);
    edge_kernel<<<2048, 128>>>(pos, ei, cen, wid, shw, shb, w1, b1, w2, b2, E);
    node_kernel<<<592, 256, N_SMEM_BYTES>>>(pos, zinc, cen, wid, shw, shb,
                                            znw, znb, npw, npb, lng, lnb,
                                            (float*)d_out, N);
}